// round 11
// baseline (speedup 1.0000x reference)
#include <cuda_runtime.h>
#include <cuda_fp16.h>
#include <cstdint>
#include <stdint.h>

#define DEPTH 15
#define N_NODES ((1 << DEPTH) - 1)   // 32767
#define DD 512
#define HH 512
#define G4 2048                      // gate cols packed [i | o | u | f]
#define AST 40                       // halfs per padded smem row (80 B)
#define SLABB (128 * AST * 2)        // bytes per slab (10240)
#define NSTAGE 4
#define NCTA_PERS 160

// ---------------- scratch ----------------
__device__ __half g_P[(size_t)N_NODES * G4];    // fp16 pre-activations
__device__ __half g_Giou[(size_t)8192 * 1536];  // fp16
__device__ __half g_Gf[(size_t)16384 * HH];     // fp16
__device__ __half g_h[(size_t)N_NODES * HH];    // fp16 h (GEMM input)
__device__ float g_c[(size_t)N_NODES * HH];     // full-precision c
__device__ __half g_hs[(size_t)8192 * HH];      // pair-summed h (fp16)
__device__ __half g_xr[(size_t)N_NODES * DD];   // fp16 x
__device__ float g_h0[HH];                      // full-precision h of node 0
__device__ __half g_Wx[(size_t)G4 * DD];
__device__ __half g_Wh[(size_t)G4 * HH];
__device__ float g_b[G4];
__device__ unsigned int g_bar_cnt;
__device__ unsigned int g_bar_rel;

// ---------------- helpers ----------------
__device__ __forceinline__ float tanh_fast(float x) {
    float y;
    asm("tanh.approx.f32 %0, %1;" : "=f"(y) : "f"(x));
    return y;
}
__device__ __forceinline__ float sig_fast(float x) {
    return 0.5f * tanh_fast(0.5f * x) + 0.5f;
}
__device__ __forceinline__ float4 ldh4(const __half* p) {
    __half2 a = *(const __half2*)p;
    __half2 b = *(const __half2*)(p + 2);
    float2 fa = __half22float2(a), fb = __half22float2(b);
    return make_float4(fa.x, fa.y, fb.x, fb.y);
}

// ---------------- prep: pack weights [i|o|u|f] + convert x ----------------
__global__ void prep(const float* __restrict__ x,
                     const float* __restrict__ Wi, const float* __restrict__ bi,
                     const float* __restrict__ Wf, const float* __restrict__ bf,
                     const float* __restrict__ Wo, const float* __restrict__ bo,
                     const float* __restrict__ Wu, const float* __restrict__ bu) {
    int idx = blockIdx.x * blockDim.x + threadIdx.x;
    if (idx < G4 * DD) {
        int row = idx >> 9;
        int col = idx & 511;
        int r = row & 511;
        int g = row >> 9;          // 0=i,1=o,2=u,3=f
        const float* W = (g == 0) ? Wi : (g == 1) ? Wo : (g == 2) ? Wu : Wf;
        const float* src = W + (size_t)r * (DD + HH);
        g_Wx[idx] = __float2half_rn(src[col]);
        g_Wh[idx] = __float2half_rn(src[DD + col]);
    }
    if (idx < G4) {
        int g = idx >> 9, r = idx & 511;
        const float* b = (g == 0) ? bi : (g == 1) ? bo : (g == 2) ? bu : bf;
        g_b[idx] = b[r];
    }
    if (idx < N_NODES * (DD / 4)) {
        float4 v = *(const float4*)(x + (size_t)idx * 4);
        __half2* dst = (__half2*)(g_xr + (size_t)idx * 4);
        dst[0] = __floats2half2_rn(v.x, v.y);
        dst[1] = __floats2half2_rn(v.z, v.w);
    }
}

// ---------------- fp16 GEMM tile: 4-stage cp.async + ldmatrix + m16n8k16 -----
// C[bm:bm+128, bn:bn+128] = A(M x 512) @ W(rows x 512)^T, fp16 out, opt bias
__device__ __forceinline__ void gemm_tile(const __half* __restrict__ A,
                                          const __half* __restrict__ W,
                                          __half* __restrict__ C,
                                          int M, int ldC,
                                          const float* __restrict__ bias,
                                          int bm, int bn, __half* smem) {
    const int tid = threadIdx.x;
    const int lane = tid & 31;
    const int wid = tid >> 5;
    const int wm = (wid >> 2) << 6;   // 0 / 64
    const int wn = (wid & 3) << 5;    // 0 / 32 / 64 / 96
    const int g = lane >> 2;
    const int tig = lane & 3;

    const unsigned int smem_u = (unsigned int)__cvta_generic_to_shared(smem);

    // ldmatrix lane bases (bytes within slab, without ks term)
    int a_base[4];
#pragma unroll
    for (int mt = 0; mt < 4; mt++)
        a_base[mt] = (wm + mt * 16 + (lane & 15)) * 80 + ((lane >> 4) & 1) * 16;
    int b_base[2];
#pragma unroll
    for (int ntp = 0; ntp < 2; ntp++)
        b_base[ntp] = (wn + ntp * 16 + ((lane >> 4) << 3) + (lane & 7)) * 80 +
                      ((lane >> 3) & 1) * 16;

    float acc[4][4][4];
#pragma unroll
    for (int mt = 0; mt < 4; mt++)
#pragma unroll
        for (int nt = 0; nt < 4; nt++)
#pragma unroll
            for (int r = 0; r < 4; r++) acc[mt][nt][r] = 0.f;

    auto issue = [&](int buf, int K0) {   // K0 in halfs
        unsigned int sb = smem_u + buf * 2 * SLABB;
#pragma unroll
        for (int i = 0; i < 2; i++) {
            int id = tid + i * 256;
            int row = id & 127;
            int q = id >> 7;
            int gr = bm + row;
            int zf = (gr < M) ? 16 : 0;
            const __half* src = A + (size_t)(zf ? gr : 0) * DD + K0 + q * 8;
            asm volatile("cp.async.cg.shared.global [%0], [%1], 16, %2;"
                         :: "r"(sb + (unsigned)(row * 80 + q * 16)),
                            "l"(src), "r"(zf));
        }
        unsigned int sbw = sb + SLABB;
#pragma unroll
        for (int i = 0; i < 2; i++) {
            int id = tid + i * 256;
            int row = id & 127;
            int q = id >> 7;
            const __half* src = W + (size_t)(bn + row) * DD + K0 + q * 8;
            asm volatile("cp.async.cg.shared.global [%0], [%1], 16;"
                         :: "r"(sbw + (unsigned)(row * 80 + q * 16)),
                            "l"(src));
        }
        asm volatile("cp.async.commit_group;");
    };

    issue(0, 0);
    issue(1, 32);
    issue(2, 64);
    int bfill = 3, bread = 0;

    for (int s = 0; s < 16; s++) {
        if (s <= 13)      asm volatile("cp.async.wait_group 2;");
        else if (s == 14) asm volatile("cp.async.wait_group 1;");
        else              asm volatile("cp.async.wait_group 0;");
        __syncthreads();
        if (s + 3 < 16) {
            issue(bfill, (s + 3) * 32);
            if (++bfill == NSTAGE) bfill = 0;
        }

        unsigned int As = smem_u + bread * 2 * SLABB;
        unsigned int Ws = As + SLABB;
        if (++bread == NSTAGE) bread = 0;

#pragma unroll
        for (int ks = 0; ks < 2; ks++) {
            const int kb = ks * 32;
            unsigned int a[4][4];
#pragma unroll
            for (int mt = 0; mt < 4; mt++) {
                asm volatile("ldmatrix.sync.aligned.m8n8.x4.shared.b16 "
                             "{%0,%1,%2,%3}, [%4];"
                             : "=r"(a[mt][0]), "=r"(a[mt][1]),
                               "=r"(a[mt][2]), "=r"(a[mt][3])
                             : "r"(As + (unsigned)(a_base[mt] + kb)));
            }
            unsigned int b[2][4];
#pragma unroll
            for (int ntp = 0; ntp < 2; ntp++) {
                asm volatile("ldmatrix.sync.aligned.m8n8.x4.shared.b16 "
                             "{%0,%1,%2,%3}, [%4];"
                             : "=r"(b[ntp][0]), "=r"(b[ntp][1]),
                               "=r"(b[ntp][2]), "=r"(b[ntp][3])
                             : "r"(Ws + (unsigned)(b_base[ntp] + kb)));
            }
#pragma unroll
            for (int mt = 0; mt < 4; mt++)
#pragma unroll
                for (int nt = 0; nt < 4; nt++) {
                    float* c = acc[mt][nt];
                    unsigned int b0 = b[nt >> 1][(nt & 1) * 2];
                    unsigned int b1 = b[nt >> 1][(nt & 1) * 2 + 1];
                    asm volatile(
                        "mma.sync.aligned.m16n8k16.row.col.f32.f16.f16.f32 "
                        "{%0,%1,%2,%3}, {%4,%5,%6,%7}, {%8,%9}, {%0,%1,%2,%3};"
                        : "+f"(c[0]), "+f"(c[1]), "+f"(c[2]), "+f"(c[3])
                        : "r"(a[mt][0]), "r"(a[mt][1]), "r"(a[mt][2]), "r"(a[mt][3]),
                          "r"(b0), "r"(b1));
                }
        }
    }
    __syncthreads();   // protect smem before next tile / reuse

#pragma unroll
    for (int mt = 0; mt < 4; mt++) {
        int row0 = bm + wm + (mt << 4) + g;
#pragma unroll
        for (int nt = 0; nt < 4; nt++) {
            int col = bn + wn + (nt << 3) + (tig << 1);
            float b0 = 0.f, b1 = 0.f;
            if (bias) { b0 = bias[col]; b1 = bias[col + 1]; }
            if (row0 < M) {
                *(__half2*)(C + (size_t)row0 * ldC + col) =
                    __floats2half2_rn(acc[mt][nt][0] + b0, acc[mt][nt][1] + b1);
            }
            if (row0 + 8 < M) {
                *(__half2*)(C + (size_t)(row0 + 8) * ldC + col) =
                    __floats2half2_rn(acc[mt][nt][2] + b0, acc[mt][nt][3] + b1);
            }
        }
    }
}

// ---------------- merged big-P GEMM: iou (all nodes) + f (internal) ----------
#define TILES_P_IOU (12 * 256)
__global__ __launch_bounds__(256, 2) void big_P_gemm() {
    extern __shared__ __half smem[];
    int t = blockIdx.x;
    if (t < TILES_P_IOU) {
        int by = t / 12, bx = t % 12;
        gemm_tile(g_xr, g_Wx, g_P, N_NODES, G4, g_b, by * 128, bx * 128, smem);
    } else {
        int t2 = t - TILES_P_IOU;
        int by = t2 >> 2, bx = t2 & 3;
        gemm_tile(g_xr, g_Wx + (size_t)1536 * DD, g_P + 1536,
                  (1 << (DEPTH - 1)) - 1, G4, g_b + 1536, by * 128, bx * 128, smem);
    }
}

// ---------------- merged level GEMMs ----------------
__global__ __launch_bounds__(256, 2) void level_gemms(int cnt) {
    extern __shared__ __half smem[];
    int cs = 2 * cnt - 1;
    int tiles_i = (cnt >> 7) * 12;
    int t = blockIdx.x;
    if (t < tiles_i) {
        int by = t / 12, bx = t % 12;
        gemm_tile(g_hs, g_Wh, g_Giou, cnt, 1536, nullptr, by * 128, bx * 128, smem);
    } else {
        int t2 = t - tiles_i;
        int by = t2 >> 2, bx = t2 & 3;
        gemm_tile(g_h + (size_t)cs * HH, g_Wh + (size_t)(3 * HH) * DD,
                  g_Gf, 2 * cnt, 512, nullptr, by * 128, bx * 128, smem);
    }
}

// ---------------- combine unit (fused pair-sum) ----------------
__device__ __forceinline__ void combine_unit(int u, int U, int start, int cs,
                                             bool write_hs, float4* sh) {
    float4 hfull = make_float4(0.f, 0.f, 0.f, 0.f);
    int b = u >> 7, j4 = (u & 127) << 2;
    if (u < U) {
        size_t n = (size_t)(start + b);
        const __half* Pp = g_P + n * G4;
        const __half* Gi = g_Giou + (size_t)b * 1536;
        float4 pi = ldh4(Pp + j4);
        float4 po = ldh4(Pp + HH + j4);
        float4 pu = ldh4(Pp + 2 * HH + j4);
        float4 pf = ldh4(Pp + 3 * HH + j4);
        float4 gi = ldh4(Gi + j4);
        float4 go = ldh4(Gi + HH + j4);
        float4 gu = ldh4(Gi + 2 * HH + j4);
        float4 gfl = ldh4(g_Gf + (size_t)(2 * b) * HH + j4);
        float4 gfr = ldh4(g_Gf + (size_t)(2 * b + 1) * HH + j4);
        float4 cl = *(const float4*)(g_c + (size_t)(cs + 2 * b) * HH + j4);
        float4 cr = *(const float4*)(g_c + (size_t)(cs + 2 * b + 1) * HH + j4);
        float4 c4;
#define COMB(X)                                                  \
        {                                                        \
            float i_ = sig_fast(pi.X + gi.X);                    \
            float o_ = sig_fast(po.X + go.X);                    \
            float u_ = tanh_fast(pu.X + gu.X);                   \
            float fl_ = sig_fast(pf.X + gfl.X);                  \
            float fr_ = sig_fast(pf.X + gfr.X);                  \
            c4.X = i_ * u_ + fl_ * cl.X + fr_ * cr.X;            \
            hfull.X = o_ * tanh_fast(c4.X);                      \
        }
        COMB(x) COMB(y) COMB(z) COMB(w)
#undef COMB
        *(float4*)(g_c + n * HH + j4) = c4;
        __half2* hd = (__half2*)(g_h + n * HH + j4);
        hd[0] = __floats2half2_rn(hfull.x, hfull.y);
        hd[1] = __floats2half2_rn(hfull.z, hfull.w);
        if (n == 0) *(float4*)(g_h0 + j4) = hfull;
    }
    sh[threadIdx.x] = hfull;
    __syncthreads();
    if (write_hs && threadIdx.x < 128 && u < U) {
        float4 o = sh[threadIdx.x + 128];
        __half2* hd = (__half2*)(g_hs + (size_t)(b >> 1) * HH + j4);
        hd[0] = __floats2half2_rn(hfull.x + o.x, hfull.y + o.y);
        hd[1] = __floats2half2_rn(hfull.z + o.z, hfull.w + o.w);
    }
    __syncthreads();
}

// ---------------- big-level combine ----------------
__global__ void combine_big(int start, int cnt, int cs) {
    __shared__ float4 sh[256];
    int u = blockIdx.x * 256 + threadIdx.x;
    combine_unit(u, cnt << 7, start, cs, true, sh);
}

// ---------------- leaf level (+ fused pair-sum) ----------------
__global__ void leaf_kernel() {
    __shared__ float4 sh[256];
    int u = blockIdx.x * 256 + threadIdx.x;
    int b = u >> 7, j4 = (u & 127) << 2;
    size_t n = (size_t)((1 << (DEPTH - 1)) - 1 + b);
    const __half* Pp = g_P + n * G4;
    float4 pi = ldh4(Pp + j4);
    float4 po = ldh4(Pp + HH + j4);
    float4 pu = ldh4(Pp + 2 * HH + j4);
    float4 c4, hfull;
#define LEAF1(X)                                             \
    {                                                        \
        float i_ = sig_fast(pi.X), o_ = sig_fast(po.X);      \
        float u_ = tanh_fast(pu.X);                          \
        c4.X = i_ * u_;                                      \
        hfull.X = o_ * tanh_fast(c4.X);                      \
    }
    LEAF1(x) LEAF1(y) LEAF1(z) LEAF1(w)
#undef LEAF1
    *(float4*)(g_c + n * HH + j4) = c4;
    __half2* hd = (__half2*)(g_h + n * HH + j4);
    hd[0] = __floats2half2_rn(hfull.x, hfull.y);
    hd[1] = __floats2half2_rn(hfull.z, hfull.w);
    sh[threadIdx.x] = hfull;
    __syncthreads();
    if (threadIdx.x < 128) {
        float4 o = sh[threadIdx.x + 128];
        __half2* hs = (__half2*)(g_hs + (size_t)(b >> 1) * HH + j4);
        hs[0] = __floats2half2_rn(hfull.x + o.x, hfull.y + o.y);
        hs[1] = __floats2half2_rn(hfull.z + o.z, hfull.w + o.w);
    }
}

// ---------------- software grid barrier (replay-safe) ----------------
__device__ __forceinline__ void grid_sync(unsigned int gen, unsigned int rel_base) {
    __syncthreads();
    if (threadIdx.x == 0) {
        __threadfence();
        unsigned int a = atomicAdd(&g_bar_cnt, 1);
        if (a == NCTA_PERS - 1) {
            g_bar_cnt = 0;
            __threadfence();
            atomicAdd(&g_bar_rel, 1);
        } else {
            while (*(volatile unsigned int*)&g_bar_rel - rel_base < gen) { }
        }
        __threadfence();
    }
    __syncthreads();
}

// ---------------- persistent kernel: levels 10..0 + output ----------------
__global__ __launch_bounds__(256) void small_levels(float* __restrict__ out,
                                                    int out_size) {
    extern __shared__ __half smem[];
    unsigned int rel_base = *(volatile unsigned int*)&g_bar_rel;
    unsigned int gen = 0;
    for (int lvl = 10; lvl >= 0; lvl--) {
        int cnt = 1 << lvl;
        int start = cnt - 1;
        int cs = 2 * cnt - 1;
        int tiles_i = ((cnt + 127) >> 7) * 12;
        int tiles_f = ((2 * cnt + 127) >> 7) * 4;
        int tot = tiles_i + tiles_f;
        for (int t = blockIdx.x; t < tot; t += NCTA_PERS) {
            if (t < tiles_i) {
                int by = t / 12, bx = t % 12;
                gemm_tile(g_hs, g_Wh, g_Giou, cnt, 1536, nullptr,
                          by * 128, bx * 128, smem);
            } else {
                int t2 = t - tiles_i;
                int by = t2 >> 2, bx = t2 & 3;
                gemm_tile(g_h + (size_t)cs * HH, g_Wh + (size_t)(3 * HH) * DD,
                          g_Gf, 2 * cnt, 512, nullptr, by * 128, bx * 128, smem);
            }
        }
        gen++; grid_sync(gen, rel_base);
        int U = cnt << 7;
        for (int base = blockIdx.x * 256; base < U; base += NCTA_PERS * 256) {
            combine_unit(base + (int)threadIdx.x, U, start, cs, lvl > 0,
                         (float4*)smem);
        }
        gen++; grid_sync(gen, rel_base);
    }
    // output: [h[0] | c[0]] (barrier above made lvl-0 results visible)
    if (blockIdx.x == 0) {
        for (int j = threadIdx.x; j < HH; j += 256) {
            if (j < out_size) out[j] = g_h0[j];
            if (j + HH < out_size) out[j + HH] = g_c[j];
        }
    }
}

extern "C" void kernel_launch(void* const* d_in, const int* in_sizes, int n_in,
                              void* d_out, int out_size) {
    const float* x  = (const float*)d_in[0];
    const float* Wi = (const float*)d_in[1];
    const float* bi = (const float*)d_in[2];
    const float* Wf = (const float*)d_in[3];
    const float* bf = (const float*)d_in[4];
    const float* Wo = (const float*)d_in[5];
    const float* bo = (const float*)d_in[6];
    const float* Wu = (const float*)d_in[7];
    const float* bu = (const float*)d_in[8];
    float* out = (float*)d_out;

    const int SMEM_GEMM = 2 * NSTAGE * SLABB;   // 81920 B (4 stages x 2 slabs)
    cudaFuncSetAttribute(big_P_gemm,
                         cudaFuncAttributeMaxDynamicSharedMemorySize, SMEM_GEMM);
    cudaFuncSetAttribute(level_gemms,
                         cudaFuncAttributeMaxDynamicSharedMemorySize, SMEM_GEMM);
    cudaFuncSetAttribute(small_levels,
                         cudaFuncAttributeMaxDynamicSharedMemorySize, SMEM_GEMM);

    // prep covers both weight packing (1M idx) and x conversion (4.19M idx)
    prep<<<(N_NODES * (DD / 4) + 255) / 256, 256>>>(x, Wi, bi, Wf, bf, Wo, bo, Wu, bu);

    // P: iou for all nodes + f for internal nodes, one launch
    {
        int grid = TILES_P_IOU + 4 * 128;
        big_P_gemm<<<grid, 256, SMEM_GEMM>>>();
    }

    // leaves (+ pair-sum for level 13)
    leaf_kernel<<<(1 << (DEPTH - 1)) * 128 / 256, 256>>>();

    // big internal levels 13..11
    for (int lvl = DEPTH - 2; lvl >= 11; lvl--) {
        int cnt = 1 << lvl;
        int start = cnt - 1;
        int cs = 2 * cnt - 1;
        int grid = (cnt >> 7) * 12 + ((2 * cnt) >> 7) * 4;
        level_gemms<<<grid, 256, SMEM_GEMM>>>(cnt);
        combine_big<<<cnt * 128 / 256, 256>>>(start, cnt, cs);
    }

    // levels 10..0 in one persistent launch (+ fused output write)
    small_levels<<<NCTA_PERS, 256, SMEM_GEMM>>>(out, out_size);
}

// round 13
// speedup vs baseline: 1.4635x; 1.4635x over previous
#include <cuda_runtime.h>
#include <cuda_fp16.h>
#include <cstdint>
#include <stdint.h>

#define DEPTH 15
#define N_NODES ((1 << DEPTH) - 1)   // 32767
#define DD 512
#define HH 512
#define G4 2048                      // gate cols packed [i | o | u | f]
#define AST 72                       // halfs per padded smem row (144 B)
#define SLABB (128 * AST * 2)        // bytes per A-or-B slab (18432)
#define STAGEB (2 * SLABB)           // 36864 B per stage
#define NSTG 3
#define SMEM_GEMM (NSTG * STAGEB)    // 110592 B
#define NCTA_PERS 160

// ---------------- scratch ----------------
__device__ __half g_P[(size_t)N_NODES * G4];    // fp16 pre-activations
__device__ __half g_Giou[(size_t)8192 * 1536];  // fp16
__device__ __half g_Gf[(size_t)16384 * HH];     // fp16
__device__ __half g_h[(size_t)N_NODES * HH];    // fp16 h (GEMM input)
__device__ float g_c[(size_t)N_NODES * HH];     // full-precision c
__device__ __half g_hs[(size_t)8192 * HH];      // pair-summed h (fp16)
__device__ __half g_xr[(size_t)N_NODES * DD];   // fp16 x
__device__ float g_h0[HH];                      // full-precision h of node 0
__device__ __half g_Wx[(size_t)G4 * DD];
__device__ __half g_Wh[(size_t)G4 * HH];
__device__ float g_b[G4];
__device__ unsigned int g_bar_cnt;
__device__ unsigned int g_bar_rel;

// ---------------- helpers ----------------
__device__ __forceinline__ float tanh_fast(float x) {
    float y;
    asm("tanh.approx.f32 %0, %1;" : "=f"(y) : "f"(x));
    return y;
}
__device__ __forceinline__ float sig_fast(float x) {
    return 0.5f * tanh_fast(0.5f * x) + 0.5f;
}
__device__ __forceinline__ float4 ldh4(const __half* p) {
    __half2 a = *(const __half2*)p;
    __half2 b = *(const __half2*)(p + 2);
    float2 fa = __half22float2(a), fb = __half22float2(b);
    return make_float4(fa.x, fa.y, fb.x, fb.y);
}

// ---------------- prep: pack weights [i|o|u|f] + convert x ----------------
__global__ void prep(const float* __restrict__ x,
                     const float* __restrict__ Wi, const float* __restrict__ bi,
                     const float* __restrict__ Wf, const float* __restrict__ bf,
                     const float* __restrict__ Wo, const float* __restrict__ bo,
                     const float* __restrict__ Wu, const float* __restrict__ bu) {
    int idx = blockIdx.x * blockDim.x + threadIdx.x;
    if (idx < G4 * DD) {
        int row = idx >> 9;
        int col = idx & 511;
        int r = row & 511;
        int g = row >> 9;          // 0=i,1=o,2=u,3=f
        const float* W = (g == 0) ? Wi : (g == 1) ? Wo : (g == 2) ? Wu : Wf;
        const float* src = W + (size_t)r * (DD + HH);
        g_Wx[idx] = __float2half_rn(src[col]);
        g_Wh[idx] = __float2half_rn(src[DD + col]);
    }
    if (idx < G4) {
        int g = idx >> 9, r = idx & 511;
        const float* b = (g == 0) ? bi : (g == 1) ? bo : (g == 2) ? bu : bf;
        g_b[idx] = b[r];
    }
    if (idx < N_NODES * (DD / 4)) {
        float4 v = *(const float4*)(x + (size_t)idx * 4);
        __half2* dst = (__half2*)(g_xr + (size_t)idx * 4);
        dst[0] = __floats2half2_rn(v.x, v.y);
        dst[1] = __floats2half2_rn(v.z, v.w);
    }
}

// ---------------- fp16 GEMM tile: K=64 stages, 3-buf cp.async + ldmatrix -----
// C[bm:bm+128, bn:bn+128] = A(M x 512) @ W(rows x 512)^T, fp16 out, opt bias
__device__ __forceinline__ void gemm_tile(const __half* __restrict__ A,
                                          const __half* __restrict__ W,
                                          __half* __restrict__ C,
                                          int M, int ldC,
                                          const float* __restrict__ bias,
                                          int bm, int bn, __half* smem) {
    const int tid = threadIdx.x;
    const int lane = tid & 31;
    const int wid = tid >> 5;
    const int wm = (wid >> 2) << 6;   // 0 / 64
    const int wn = (wid & 3) << 5;    // 0 / 32 / 64 / 96
    const int g = lane >> 2;
    const int tig = lane & 3;

    const unsigned int smem_u = (unsigned int)__cvta_generic_to_shared(smem);

    // ldmatrix lane bases (bytes within slab; + ks*32 selects K=16 chunk)
    int a_base[4];
#pragma unroll
    for (int mt = 0; mt < 4; mt++)
        a_base[mt] = (wm + mt * 16 + (lane & 15)) * 144 + ((lane >> 4) & 1) * 16;
    int b_base[2];
#pragma unroll
    for (int ntp = 0; ntp < 2; ntp++)
        b_base[ntp] = (wn + ntp * 16 + ((lane >> 4) << 3) + (lane & 7)) * 144 +
                      ((lane >> 3) & 1) * 16;

    float acc[4][4][4];
#pragma unroll
    for (int mt = 0; mt < 4; mt++)
#pragma unroll
        for (int nt = 0; nt < 4; nt++)
#pragma unroll
            for (int r = 0; r < 4; r++) acc[mt][nt][r] = 0.f;

    // stage = one K-chunk of 64 halfs (128 B per row); 8 chunks per row,
    // 1024 16B-chunks per slab, 4 per thread per slab
    auto issue = [&](int buf, int s) {
        int K0 = s << 6;
        unsigned int sb = smem_u + buf * STAGEB;
#pragma unroll
        for (int i = 0; i < 4; i++) {
            int id = tid + i * 256;
            int row = id >> 3;            // 0..127
            int q = id & 7;               // 16B chunk within 128B of data
            int gr = bm + row;
            int zf = (gr < M) ? 16 : 0;
            const __half* src = A + (size_t)(zf ? gr : 0) * DD + K0 + q * 8;
            asm volatile("cp.async.cg.shared.global [%0], [%1], 16, %2;"
                         :: "r"(sb + (unsigned)(row * 144 + q * 16)),
                            "l"(src), "r"(zf));
        }
        unsigned int sbw = sb + SLABB;
#pragma unroll
        for (int i = 0; i < 4; i++) {
            int id = tid + i * 256;
            int row = id >> 3;
            int q = id & 7;
            const __half* src = W + (size_t)(bn + row) * DD + K0 + q * 8;
            asm volatile("cp.async.cg.shared.global [%0], [%1], 16;"
                         :: "r"(sbw + (unsigned)(row * 144 + q * 16)),
                            "l"(src));
        }
        asm volatile("cp.async.commit_group;");
    };

    issue(0, 0);
    issue(1, 1);

    for (int s = 0; s < 8; s++) {
        if (s < 7) asm volatile("cp.async.wait_group 1;");
        else       asm volatile("cp.async.wait_group 0;");
        __syncthreads();
        if (s + 2 < 8) issue((s + 2) % NSTG, s + 2);

        unsigned int As = smem_u + (s % NSTG) * STAGEB;
        unsigned int Ws = As + SLABB;

#pragma unroll
        for (int ks = 0; ks < 4; ks++) {
            const int kb = ks * 32;
            unsigned int a[4][4];
#pragma unroll
            for (int mt = 0; mt < 4; mt++) {
                asm volatile("ldmatrix.sync.aligned.m8n8.x4.shared.b16 "
                             "{%0,%1,%2,%3}, [%4];"
                             : "=r"(a[mt][0]), "=r"(a[mt][1]),
                               "=r"(a[mt][2]), "=r"(a[mt][3])
                             : "r"(As + (unsigned)(a_base[mt] + kb)));
            }
            unsigned int b[2][4];
#pragma unroll
            for (int ntp = 0; ntp < 2; ntp++) {
                asm volatile("ldmatrix.sync.aligned.m8n8.x4.shared.b16 "
                             "{%0,%1,%2,%3}, [%4];"
                             : "=r"(b[ntp][0]), "=r"(b[ntp][1]),
                               "=r"(b[ntp][2]), "=r"(b[ntp][3])
                             : "r"(Ws + (unsigned)(b_base[ntp] + kb)));
            }
#pragma unroll
            for (int mt = 0; mt < 4; mt++)
#pragma unroll
                for (int nt = 0; nt < 4; nt++) {
                    float* c = acc[mt][nt];
                    unsigned int b0 = b[nt >> 1][(nt & 1) * 2];
                    unsigned int b1 = b[nt >> 1][(nt & 1) * 2 + 1];
                    asm volatile(
                        "mma.sync.aligned.m16n8k16.row.col.f32.f16.f16.f32 "
                        "{%0,%1,%2,%3}, {%4,%5,%6,%7}, {%8,%9}, {%0,%1,%2,%3};"
                        : "+f"(c[0]), "+f"(c[1]), "+f"(c[2]), "+f"(c[3])
                        : "r"(a[mt][0]), "r"(a[mt][1]), "r"(a[mt][2]), "r"(a[mt][3]),
                          "r"(b0), "r"(b1));
                }
        }
    }
    __syncthreads();   // protect smem before next tile / reuse

#pragma unroll
    for (int mt = 0; mt < 4; mt++) {
        int row0 = bm + wm + (mt << 4) + g;
#pragma unroll
        for (int nt = 0; nt < 4; nt++) {
            int col = bn + wn + (nt << 3) + (tig << 1);
            float b0 = 0.f, b1 = 0.f;
            if (bias) { b0 = bias[col]; b1 = bias[col + 1]; }
            if (row0 < M) {
                *(__half2*)(C + (size_t)row0 * ldC + col) =
                    __floats2half2_rn(acc[mt][nt][0] + b0, acc[mt][nt][1] + b1);
            }
            if (row0 + 8 < M) {
                *(__half2*)(C + (size_t)(row0 + 8) * ldC + col) =
                    __floats2half2_rn(acc[mt][nt][2] + b0, acc[mt][nt][3] + b1);
            }
        }
    }
}

// ---------------- merged big-P GEMM: iou (all nodes) + f (internal) ----------
#define TILES_P_IOU (12 * 256)
__global__ __launch_bounds__(256, 2) void big_P_gemm() {
    extern __shared__ __half smem[];
    int t = blockIdx.x;
    if (t < TILES_P_IOU) {
        int by = t / 12, bx = t % 12;
        gemm_tile(g_xr, g_Wx, g_P, N_NODES, G4, g_b, by * 128, bx * 128, smem);
    } else {
        int t2 = t - TILES_P_IOU;
        int by = t2 >> 2, bx = t2 & 3;
        gemm_tile(g_xr, g_Wx + (size_t)1536 * DD, g_P + 1536,
                  (1 << (DEPTH - 1)) - 1, G4, g_b + 1536, by * 128, bx * 128, smem);
    }
}

// ---------------- merged level GEMMs ----------------
__global__ __launch_bounds__(256, 2) void level_gemms(int cnt) {
    extern __shared__ __half smem[];
    int cs = 2 * cnt - 1;
    int tiles_i = (cnt >> 7) * 12;
    int t = blockIdx.x;
    if (t < tiles_i) {
        int by = t / 12, bx = t % 12;
        gemm_tile(g_hs, g_Wh, g_Giou, cnt, 1536, nullptr, by * 128, bx * 128, smem);
    } else {
        int t2 = t - tiles_i;
        int by = t2 >> 2, bx = t2 & 3;
        gemm_tile(g_h + (size_t)cs * HH, g_Wh + (size_t)(3 * HH) * DD,
                  g_Gf, 2 * cnt, 512, nullptr, by * 128, bx * 128, smem);
    }
}

// ---------------- combine unit (fused pair-sum) ----------------
__device__ __forceinline__ void combine_unit(int u, int U, int start, int cs,
                                             bool write_hs, float4* sh) {
    float4 hfull = make_float4(0.f, 0.f, 0.f, 0.f);
    int b = u >> 7, j4 = (u & 127) << 2;
    if (u < U) {
        size_t n = (size_t)(start + b);
        const __half* Pp = g_P + n * G4;
        const __half* Gi = g_Giou + (size_t)b * 1536;
        float4 pi = ldh4(Pp + j4);
        float4 po = ldh4(Pp + HH + j4);
        float4 pu = ldh4(Pp + 2 * HH + j4);
        float4 pf = ldh4(Pp + 3 * HH + j4);
        float4 gi = ldh4(Gi + j4);
        float4 go = ldh4(Gi + HH + j4);
        float4 gu = ldh4(Gi + 2 * HH + j4);
        float4 gfl = ldh4(g_Gf + (size_t)(2 * b) * HH + j4);
        float4 gfr = ldh4(g_Gf + (size_t)(2 * b + 1) * HH + j4);
        float4 cl = *(const float4*)(g_c + (size_t)(cs + 2 * b) * HH + j4);
        float4 cr = *(const float4*)(g_c + (size_t)(cs + 2 * b + 1) * HH + j4);
        float4 c4;
#define COMB(X)                                                  \
        {                                                        \
            float i_ = sig_fast(pi.X + gi.X);                    \
            float o_ = sig_fast(po.X + go.X);                    \
            float u_ = tanh_fast(pu.X + gu.X);                   \
            float fl_ = sig_fast(pf.X + gfl.X);                  \
            float fr_ = sig_fast(pf.X + gfr.X);                  \
            c4.X = i_ * u_ + fl_ * cl.X + fr_ * cr.X;            \
            hfull.X = o_ * tanh_fast(c4.X);                      \
        }
        COMB(x) COMB(y) COMB(z) COMB(w)
#undef COMB
        *(float4*)(g_c + n * HH + j4) = c4;
        __half2* hd = (__half2*)(g_h + n * HH + j4);
        hd[0] = __floats2half2_rn(hfull.x, hfull.y);
        hd[1] = __floats2half2_rn(hfull.z, hfull.w);
        if (n == 0) *(float4*)(g_h0 + j4) = hfull;
    }
    sh[threadIdx.x] = hfull;
    __syncthreads();
    if (write_hs && threadIdx.x < 128 && u < U) {
        float4 o = sh[threadIdx.x + 128];
        __half2* hd = (__half2*)(g_hs + (size_t)(b >> 1) * HH + j4);
        hd[0] = __floats2half2_rn(hfull.x + o.x, hfull.y + o.y);
        hd[1] = __floats2half2_rn(hfull.z + o.z, hfull.w + o.w);
    }
    __syncthreads();
}

// ---------------- big-level combine ----------------
__global__ void combine_big(int start, int cnt, int cs) {
    __shared__ float4 sh[256];
    int u = blockIdx.x * 256 + threadIdx.x;
    combine_unit(u, cnt << 7, start, cs, true, sh);
}

// ---------------- leaf level (+ fused pair-sum) ----------------
__global__ void leaf_kernel() {
    __shared__ float4 sh[256];
    int u = blockIdx.x * 256 + threadIdx.x;
    int b = u >> 7, j4 = (u & 127) << 2;
    size_t n = (size_t)((1 << (DEPTH - 1)) - 1 + b);
    const __half* Pp = g_P + n * G4;
    float4 pi = ldh4(Pp + j4);
    float4 po = ldh4(Pp + HH + j4);
    float4 pu = ldh4(Pp + 2 * HH + j4);
    float4 c4, hfull;
#define LEAF1(X)                                             \
    {                                                        \
        float i_ = sig_fast(pi.X), o_ = sig_fast(po.X);      \
        float u_ = tanh_fast(pu.X);                          \
        c4.X = i_ * u_;                                      \
        hfull.X = o_ * tanh_fast(c4.X);                      \
    }
    LEAF1(x) LEAF1(y) LEAF1(z) LEAF1(w)
#undef LEAF1
    *(float4*)(g_c + n * HH + j4) = c4;
    __half2* hd = (__half2*)(g_h + n * HH + j4);
    hd[0] = __floats2half2_rn(hfull.x, hfull.y);
    hd[1] = __floats2half2_rn(hfull.z, hfull.w);
    sh[threadIdx.x] = hfull;
    __syncthreads();
    if (threadIdx.x < 128) {
        float4 o = sh[threadIdx.x + 128];
        __half2* hs = (__half2*)(g_hs + (size_t)(b >> 1) * HH + j4);
        hs[0] = __floats2half2_rn(hfull.x + o.x, hfull.y + o.y);
        hs[1] = __floats2half2_rn(hfull.z + o.z, hfull.w + o.w);
    }
}

// ---------------- software grid barrier (replay-safe) ----------------
__device__ __forceinline__ void grid_sync(unsigned int gen, unsigned int rel_base) {
    __syncthreads();
    if (threadIdx.x == 0) {
        __threadfence();
        unsigned int a = atomicAdd(&g_bar_cnt, 1);
        if (a == NCTA_PERS - 1) {
            g_bar_cnt = 0;
            __threadfence();
            atomicAdd(&g_bar_rel, 1);
        } else {
            while (*(volatile unsigned int*)&g_bar_rel - rel_base < gen) { }
        }
        __threadfence();
    }
    __syncthreads();
}

// ---------------- persistent kernel: levels 10..0 + output ----------------
__global__ __launch_bounds__(256) void small_levels(float* __restrict__ out,
                                                    int out_size) {
    extern __shared__ __half smem[];
    unsigned int rel_base = *(volatile unsigned int*)&g_bar_rel;
    unsigned int gen = 0;
    for (int lvl = 10; lvl >= 0; lvl--) {
        int cnt = 1 << lvl;
        int start = cnt - 1;
        int cs = 2 * cnt - 1;
        int tiles_i = ((cnt + 127) >> 7) * 12;
        int tiles_f = ((2 * cnt + 127) >> 7) * 4;
        int tot = tiles_i + tiles_f;
        for (int t = blockIdx.x; t < tot; t += NCTA_PERS) {
            if (t < tiles_i) {
                int by = t / 12, bx = t % 12;
                gemm_tile(g_hs, g_Wh, g_Giou, cnt, 1536, nullptr,
                          by * 128, bx * 128, smem);
            } else {
                int t2 = t - tiles_i;
                int by = t2 >> 2, bx = t2 & 3;
                gemm_tile(g_h + (size_t)cs * HH, g_Wh + (size_t)(3 * HH) * DD,
                          g_Gf, 2 * cnt, 512, nullptr, by * 128, bx * 128, smem);
            }
        }
        gen++; grid_sync(gen, rel_base);
        int U = cnt << 7;
        for (int base = blockIdx.x * 256; base < U; base += NCTA_PERS * 256) {
            combine_unit(base + (int)threadIdx.x, U, start, cs, lvl > 0,
                         (float4*)smem);
        }
        gen++; grid_sync(gen, rel_base);
    }
    // output: [h[0] | c[0]] (barrier above made lvl-0 results visible)
    if (blockIdx.x == 0) {
        for (int j = threadIdx.x; j < HH; j += 256) {
            if (j < out_size) out[j] = g_h0[j];
            if (j + HH < out_size) out[j + HH] = g_c[j];
        }
    }
}

extern "C" void kernel_launch(void* const* d_in, const int* in_sizes, int n_in,
                              void* d_out, int out_size) {
    const float* x  = (const float*)d_in[0];
    const float* Wi = (const float*)d_in[1];
    const float* bi = (const float*)d_in[2];
    const float* Wf = (const float*)d_in[3];
    const float* bf = (const float*)d_in[4];
    const float* Wo = (const float*)d_in[5];
    const float* bo = (const float*)d_in[6];
    const float* Wu = (const float*)d_in[7];
    const float* bu = (const float*)d_in[8];
    float* out = (float*)d_out;

    cudaFuncSetAttribute(big_P_gemm,
                         cudaFuncAttributeMaxDynamicSharedMemorySize, SMEM_GEMM);
    cudaFuncSetAttribute(level_gemms,
                         cudaFuncAttributeMaxDynamicSharedMemorySize, SMEM_GEMM);
    cudaFuncSetAttribute(small_levels,
                         cudaFuncAttributeMaxDynamicSharedMemorySize, SMEM_GEMM);

    // prep covers both weight packing (1M idx) and x conversion (4.19M idx)
    prep<<<(N_NODES * (DD / 4) + 255) / 256, 256>>>(x, Wi, bi, Wf, bf, Wo, bo, Wu, bu);

    // P: iou for all nodes + f for internal nodes, one launch
    {
        int grid = TILES_P_IOU + 4 * 128;   // 3072 + 512
        big_P_gemm<<<grid, 256, SMEM_GEMM>>>();
    }

    // leaves (+ pair-sum for level 13)
    leaf_kernel<<<(1 << (DEPTH - 1)) * 128 / 256, 256>>>();

    // big internal levels 13..11
    for (int lvl = DEPTH - 2; lvl >= 11; lvl--) {
        int cnt = 1 << lvl;
        int start = cnt - 1;
        int cs = 2 * cnt - 1;
        int grid = (cnt >> 7) * 12 + ((2 * cnt) >> 7) * 4;
        level_gemms<<<grid, 256, SMEM_GEMM>>>(cnt);
        combine_big<<<cnt * 128 / 256, 256>>>(start, cnt, cs);
    }

    // levels 10..0 in one persistent launch (+ fused output write)
    small_levels<<<NCTA_PERS, 256, SMEM_GEMM>>>(out, out_size);
}